// round 11
// baseline (speedup 1.0000x reference)
#include <cuda_runtime.h>
#include <math.h>
#include <cstdint>

#define NROWS 8192
#define DDIM  128
#define NTILE (NROWS / 128)               // 64 slabs of 128 rows
#define NTRI  (NTILE * (NTILE + 1) / 2)   // 2080 tiles

// dynamic smem layout for k_sim (double-buffered tiles)
#define SM_A0   0
#define SM_B0   16384
#define SM_A1   32768
#define SM_B1   49152
#define SM_RED  65536
#define SM_REDC 66048
#define SM_TOT  66560

// ---------------- scratch (init-free or self-resetting) ---------------------
__device__ char  g_q[NROWS * DDIM];       // int8 quantized normalized rows
__device__ float g_s[NROWS];              // per-row scale * sqrt(log2e)
__device__ float g_denom[NROWS];          // zeroed by k_normalize each run
__device__ float g_M[2 * DDIM];           // class sums; reset by final finisher
__device__ int   g_ncnt[2];               // class counts; reset by final finisher
__device__ float g_Lpart[NTILE][2];       // per-slab gated log sums
__device__ int   g_slabcnt[NTILE];        // reset by slab finisher
__device__ int   g_slabs;                 // reset by final finisher
__device__ int   g_tile;                  // reset by k_normalize
__device__ int   g_lblstride;

// ---------------- helpers ----------------------------------------------------
__device__ __forceinline__ uint32_t smem_u32(const void* p) {
    uint32_t a;
    asm("{ .reg .u64 t; cvta.to.shared.u64 t, %1; cvt.u32.u64 %0, t; }" : "=r"(a) : "l"(p));
    return a;
}
__device__ __forceinline__ float ex2f(float x) {
    float r;
    asm("ex2.approx.ftz.f32 %0, %1;" : "=f"(r) : "f"(x));
    return r;
}
__device__ __forceinline__ void ldsm_x4(uint32_t a, uint32_t& r0, uint32_t& r1,
                                        uint32_t& r2, uint32_t& r3) {
    asm volatile("ldmatrix.sync.aligned.m8n8.x4.shared.b16 {%0,%1,%2,%3}, [%4];"
                 : "=r"(r0), "=r"(r1), "=r"(r2), "=r"(r3) : "r"(a));
}
__device__ __forceinline__ void mma16832s8(int* c, uint32_t a0, uint32_t a1,
                                           uint32_t a2, uint32_t a3,
                                           uint32_t b0, uint32_t b1) {
    asm volatile(
        "mma.sync.aligned.m16n8k32.row.col.s32.s8.s8.s32 "
        "{%0,%1,%2,%3}, {%4,%5,%6,%7}, {%8,%9}, {%0,%1,%2,%3};"
        : "+r"(c[0]), "+r"(c[1]), "+r"(c[2]), "+r"(c[3])
        : "r"(a0), "r"(a1), "r"(a2), "r"(a3), "r"(b0), "r"(b1));
}
__device__ __forceinline__ int get_label(const int* l32, int i) { return l32[i * g_lblstride]; }

__device__ __forceinline__ void decode_tri(int idx, int& bi, int& bj) {
    bj = (int)((sqrtf(8.0f * (float)idx + 1.0f) - 1.0f) * 0.5f);
    while ((bj + 1) * (bj + 2) / 2 <= idx) bj++;
    while (bj * (bj + 1) / 2 > idx) bj--;
    bi = idx - bj * (bj + 1) / 2;
}

__device__ __forceinline__ void prefetch_tile(uint32_t baseA, uint32_t baseB,
                                              int i0, int j0, int tid) {
    #pragma unroll
    for (int c = 0; c < 4; c++) {
        int flat = c * 256 + tid;
        int row = flat >> 3, ch = flat & 7;
        uint32_t off = (uint32_t)(row * 128 + ((ch ^ (row & 7)) << 4));
        const char* ga = &g_q[(size_t)(i0 + row) * DDIM + ch * 16];
        const char* gb = &g_q[(size_t)(j0 + row) * DDIM + ch * 16];
        asm volatile("cp.async.cg.shared.global [%0], [%1], 16;" :: "r"(baseA + off), "l"(ga));
        asm volatile("cp.async.cg.shared.global [%0], [%1], 16;" :: "r"(baseB + off), "l"(gb));
    }
    asm volatile("cp.async.commit_group;" ::: "memory");
}
#define CP_WAIT_ALL() asm volatile("cp.async.wait_group 0;" ::: "memory")

// ---------------- K1: normalize + quantize + class sums + resets ------------
// 128 blocks x 256 threads; block b owns rows [64b, 64b+64).
__global__ void __launch_bounds__(256) k_normalize(const float* __restrict__ emb,
                                                   const int* __restrict__ l32) {
    const float SQRT_LOG2E = 1.2011224087864498f;
    int tid = threadIdx.x;
    int wid = tid >> 5, lane = tid & 31;
    int b = blockIdx.x;

    __shared__ int sdet;
    __shared__ float sM[2 * DDIM];
    __shared__ int   scnt[2];
    if (tid == 0) sdet = 0;
    sM[tid] = 0.0f;
    if (tid < 2) scnt[tid] = 0;
    __syncthreads();
    // labels are 0/1; int64 LE => odd int32 words are 0 (reads ints [1..511])
    if (l32[2 * tid + 1] != 0) atomicOr(&sdet, 1);
    __syncthreads();
    int stride = sdet ? 1 : 2;
    if (tid == 0 && b == 0) { g_lblstride = stride; g_tile = 0; }

    if (tid < 64) g_denom[b * 64 + tid] = 0.0f;

    #pragma unroll
    for (int it = 0; it < 8; it++) {
        int row = b * 64 + wid * 8 + it;
        float4 v = ((const float4*)(emb + (size_t)row * DDIM))[lane];
        float ss = v.x * v.x + v.y * v.y + v.z * v.z + v.w * v.w;
        float mx = fmaxf(fmaxf(fabsf(v.x), fabsf(v.y)), fmaxf(fabsf(v.z), fabsf(v.w)));
        #pragma unroll
        for (int o = 16; o; o >>= 1) {
            ss += __shfl_xor_sync(0xffffffffu, ss, o);
            mx = fmaxf(mx, __shfl_xor_sync(0xffffffffu, mx, o));
        }
        float r = rsqrtf(ss);
        float m = mx * r;
        float qs = 127.0f / m;
        int d = lane * 4;
        float e0 = v.x * r, e1 = v.y * r, e2 = v.z * r, e3 = v.w * r;
        char4 q = make_char4((char)__float2int_rn(e0 * qs), (char)__float2int_rn(e1 * qs),
                             (char)__float2int_rn(e2 * qs), (char)__float2int_rn(e3 * qs));
        *(char4*)&g_q[(size_t)row * DDIM + d] = q;
        int c = (l32[row * stride] == 0) ? 0 : 1;
        if (lane == 0) {
            g_s[row] = (m / 127.0f) * SQRT_LOG2E;
            atomicAdd(&scnt[c], 1);
        }
        float* sMc = &sM[c * DDIM + d];
        atomicAdd(&sMc[0], e0);
        atomicAdd(&sMc[1], e1);
        atomicAdd(&sMc[2], e2);
        atomicAdd(&sMc[3], e3);
    }
    __syncthreads();
    atomicAdd(&g_M[tid], sM[tid]);
    if (tid < 2) atomicAdd(&g_ncnt[tid], scnt[tid]);
}

// ---------------- K2: persistent double-buffered int8 MMA + loss tails ------
__global__ void __launch_bounds__(256, 2) k_sim(const int* __restrict__ l32,
                                                float* __restrict__ out) {
    extern __shared__ char smem[];
    uint32_t sb = smem_u32(smem);
    float* red  = (float*)(smem + SM_RED);
    float* redc = (float*)(smem + SM_REDC);

    int tid = threadIdx.x;
    int wid = tid >> 5, lane = tid & 31;
    int m_off = (wid >> 2) * 64;
    int n_off = (wid & 3) * 32;
    int lrow = lane >> 2;
    int lcol = (lane & 3) * 2;

    __shared__ int   sh_tn;
    __shared__ int   s_fini, s_finj, s_final;
    __shared__ float wred[8];
    __shared__ float sm0[8], sm1[8], sL0[8], sL1[8];

    if (tid < 128) { red[tid] = 0.0f; redc[tid] = 0.0f; }

    // prologue: grab first tile, prefetch into buffer 0
    if (tid == 0) sh_tn = atomicAdd(&g_tile, 1);
    __syncthreads();
    int t = sh_tn;
    bool valid = (t < NTRI);
    int bi = 0, bj = 0;
    if (valid) {
        decode_tri(t, bi, bj);
        prefetch_tile(sb + SM_A0, sb + SM_B0, bi * 128, bj * 128, tid);
    }
    int p = 0;

    while (valid) {
        int i0 = bi * 128, j0 = bj * 128;
        bool diag = (bi == bj);

        if (tid == 0) sh_tn = atomicAdd(&g_tile, 1);
        CP_WAIT_ALL();
        __syncthreads();            // buf p ready; sh_tn visible; red/redc zeroed

        int tn = sh_tn;
        bool nvalid = (tn < NTRI);
        int nbi = 0, nbj = 0;
        if (nvalid) {
            decode_tri(tn, nbi, nbj);
            prefetch_tile(sb + (p ? SM_A0 : SM_A1), sb + (p ? SM_B0 : SM_B1),
                          nbi * 128, nbj * 128, tid);
        }

        // scale prefetch into regs (latency hidden under MMA)
        float rs0a[4], rs1a[4];
        float2 csr[4];
        #pragma unroll
        for (int mt = 0; mt < 4; mt++) {
            rs0a[mt] = __ldg(&g_s[i0 + m_off + mt * 16 + lrow]);
            rs1a[mt] = __ldg(&g_s[i0 + m_off + mt * 16 + lrow + 8]);
        }
        #pragma unroll
        for (int nt = 0; nt < 4; nt++)
            csr[nt] = __ldg((const float2*)&g_s[j0 + n_off + nt * 8 + lcol]);

        uint32_t baseA = sb + (p ? SM_A1 : SM_A0);
        uint32_t baseB = sb + (p ? SM_B1 : SM_B0);

        int acc[4][4][4];
        #pragma unroll
        for (int mt = 0; mt < 4; mt++)
            #pragma unroll
            for (int nt = 0; nt < 4; nt++)
                #pragma unroll
                for (int e = 0; e < 4; e++) acc[mt][nt][e] = 0;

        uint32_t rowA = (uint32_t)(m_off + (lane & 15));
        uint32_t chA  = (uint32_t)(lane >> 4);
        uint32_t rowB = (uint32_t)(n_off + (lane & 7) + ((lane >> 4) << 3));
        uint32_t chB  = (uint32_t)((lane >> 3) & 1);

        #pragma unroll
        for (int kk = 0; kk < 4; kk++) {
            uint32_t a[4][4];
            #pragma unroll
            for (int mt = 0; mt < 4; mt++) {
                uint32_t r = rowA + mt * 16;
                uint32_t ch = (uint32_t)(kk * 2) + chA;
                ldsm_x4(baseA + r * 128 + ((ch ^ (r & 7)) << 4),
                        a[mt][0], a[mt][1], a[mt][2], a[mt][3]);
            }
            uint32_t b[4][2];
            #pragma unroll
            for (int q2 = 0; q2 < 2; q2++) {
                uint32_t r = rowB + (uint32_t)(q2 * 16);
                uint32_t ch = (uint32_t)(kk * 2) + chB;
                ldsm_x4(baseB + r * 128 + ((ch ^ (r & 7)) << 4),
                        b[2 * q2][0], b[2 * q2][1], b[2 * q2 + 1][0], b[2 * q2 + 1][1]);
            }
            #pragma unroll
            for (int mt = 0; mt < 4; mt++)
                #pragma unroll
                for (int nt = 0; nt < 4; nt++)
                    mma16832s8(acc[mt][nt], a[mt][0], a[mt][1], a[mt][2], a[mt][3],
                               b[nt][0], b[nt][1]);
        }

        // ---- epilogue: e = exp2(acc * s_i * s_j), row + col sums ----
        float colacc[4][2];
        #pragma unroll
        for (int nt = 0; nt < 4; nt++) { colacc[nt][0] = 0.0f; colacc[nt][1] = 0.0f; }

        #pragma unroll
        for (int mt = 0; mt < 4; mt++) {
            int grow0 = i0 + m_off + mt * 16 + lrow;
            float rs0 = rs0a[mt], rs1 = rs1a[mt];
            float s0 = 0.0f, s1 = 0.0f;
            #pragma unroll
            for (int nt = 0; nt < 4; nt++) {
                int gcol = j0 + n_off + nt * 8 + lcol;
                float e0 = ex2f((float)acc[mt][nt][0] * (rs0 * csr[nt].x));
                float e1 = ex2f((float)acc[mt][nt][1] * (rs0 * csr[nt].y));
                float e2 = ex2f((float)acc[mt][nt][2] * (rs1 * csr[nt].x));
                float e3 = ex2f((float)acc[mt][nt][3] * (rs1 * csr[nt].y));
                if (diag) {
                    if (gcol     == grow0)     e0 = 0.0f;
                    if (gcol + 1 == grow0)     e1 = 0.0f;
                    if (gcol     == grow0 + 8) e2 = 0.0f;
                    if (gcol + 1 == grow0 + 8) e3 = 0.0f;
                }
                s0 += e0 + e1;
                s1 += e2 + e3;
                colacc[nt][0] += e0 + e2;
                colacc[nt][1] += e1 + e3;
            }
            s0 += __shfl_xor_sync(0xffffffffu, s0, 1);
            s0 += __shfl_xor_sync(0xffffffffu, s0, 2);
            s1 += __shfl_xor_sync(0xffffffffu, s1, 1);
            s1 += __shfl_xor_sync(0xffffffffu, s1, 2);
            if ((lane & 3) == 0) {
                atomicAdd(&red[m_off + mt * 16 + lrow], s0);
                atomicAdd(&red[m_off + mt * 16 + lrow + 8], s1);
            }
        }

        if (!diag) {
            #pragma unroll
            for (int nt = 0; nt < 4; nt++) {
                #pragma unroll
                for (int h = 0; h < 2; h++) {
                    float c = colacc[nt][h];
                    c += __shfl_xor_sync(0xffffffffu, c, 4);
                    c += __shfl_xor_sync(0xffffffffu, c, 8);
                    c += __shfl_xor_sync(0xffffffffu, c, 16);
                    if (lane < 4)
                        atomicAdd(&redc[n_off + nt * 8 + (lane & 3) * 2 + h], c);
                }
            }
        }

        __syncthreads();
        if (tid < 128) {
            float rv = red[tid];
            atomicAdd(&g_denom[i0 + tid], rv);
            red[tid] = 0.0f;
            if (!diag) atomicAdd(&g_denom[j0 + tid], redc[tid]);
            redc[tid] = 0.0f;
        }
        __syncthreads();            // denom atomics issued before ticket

        // ---- slab tickets ----
        if (tid == 0) {
            __threadfence();
            s_fini = (atomicAdd(&g_slabcnt[bi], 1) == 63) ? 1 : 0;
            s_finj = (!diag && atomicAdd(&g_slabcnt[bj], 1) == 63) ? 1 : 0;
        }
        __syncthreads();
        int nfin = s_fini + s_finj;
        if (nfin) {
            __threadfence();        // acquire: slab's 64 contributions visible
            #pragma unroll
            for (int which = 0; which < 2; which++) {
                int doit = (which == 0) ? s_fini : s_finj;
                int s    = (which == 0) ? bi : bj;
                if (doit) {
                    float l0 = 0.0f, l1 = 0.0f;
                    if (tid < 128) {
                        int row = s * 128 + tid;
                        float li = logf(g_denom[row]);
                        if (get_label(l32, row) == 0) l0 = li; else l1 = li;
                    }
                    #pragma unroll
                    for (int o = 16; o; o >>= 1) {
                        l0 += __shfl_xor_sync(0xffffffffu, l0, o);
                        l1 += __shfl_xor_sync(0xffffffffu, l1, o);
                    }
                    if (lane == 0 && wid < 4) { wred[wid] = l0; wred[wid + 4] = l1; }
                    __syncthreads();
                    if (tid == 0) {
                        g_Lpart[s][0] = wred[0] + wred[1] + wred[2] + wred[3];
                        g_Lpart[s][1] = wred[4] + wred[5] + wred[6] + wred[7];
                        g_slabcnt[s] = 0;          // self-reset for next replay
                    }
                    __syncthreads();
                }
            }
            if (tid == 0) {
                __threadfence();
                int old = atomicAdd(&g_slabs, nfin);
                s_final = (old + nfin == NTILE) ? 1 : 0;
                if (s_final) g_slabs = 0;          // self-reset
            }
            __syncthreads();
            if (s_final) {
                __threadfence();
                // |Mc|^2 from g_M; reset g_M for next replay
                float Md = g_M[tid];
                g_M[tid] = 0.0f;
                float q0 = (tid < 128) ? Md * Md : 0.0f;
                float q1 = (tid < 128) ? 0.0f : Md * Md;
                #pragma unroll
                for (int o = 16; o; o >>= 1) {
                    q0 += __shfl_xor_sync(0xffffffffu, q0, o);
                    q1 += __shfl_xor_sync(0xffffffffu, q1, o);
                }
                if (lane == 0) { sm0[wid] = q0; sm1[wid] = q1; }
                float L0 = 0.0f, L1 = 0.0f;
                if (tid < NTILE) { L0 = g_Lpart[tid][0]; L1 = g_Lpart[tid][1]; }
                #pragma unroll
                for (int o = 16; o; o >>= 1) {
                    L0 += __shfl_xor_sync(0xffffffffu, L0, o);
                    L1 += __shfl_xor_sync(0xffffffffu, L1, o);
                }
                if (lane == 0) { sL0[wid] = L0; sL1[wid] = L1; }
                __syncthreads();
                if (tid == 0) {
                    float M0 = 0.0f, M1 = 0.0f, TL0 = 0.0f, TL1 = 0.0f;
                    #pragma unroll
                    for (int w = 0; w < 8; w++) {
                        M0 += sm0[w]; M1 += sm1[w];
                        TL0 += sL0[w]; TL1 += sL1[w];
                    }
                    float n0 = (float)g_ncnt[0], n1 = (float)g_ncnt[1];
                    g_ncnt[0] = 0; g_ncnt[1] = 0;  // self-reset
                    float loss0 = -M0 + n0 + (n0 - 1.0f) * TL0;
                    float loss1 = -M1 + n1 + (n1 - 1.0f) * TL1;
                    out[0] = loss0 / n0 + loss1;
                }
            }
        }

        bi = nbi; bj = nbj; valid = nvalid; p ^= 1;
    }
}

// ---------------- launch -----------------------------------------------------
extern "C" void kernel_launch(void* const* d_in, const int* in_sizes, int n_in,
                              void* d_out, int out_size) {
    const float* emb = (const float*)d_in[0];
    const int*   l32 = (const int*)d_in[1];
    float*       out = (float*)d_out;

    int dev = 0, smCount = 148;
    cudaGetDevice(&dev);
    cudaDeviceGetAttribute(&smCount, cudaDevAttrMultiProcessorCount, dev);
    int ncta = smCount * 2;

    cudaFuncSetAttribute(k_sim, cudaFuncAttributeMaxDynamicSharedMemorySize, SM_TOT);

    k_normalize<<<128, 256>>>(emb, l32);
    k_sim<<<ncta, 256, SM_TOT>>>(l32, out);
}

// round 12
// speedup vs baseline: 1.1009x; 1.1009x over previous
#include <cuda_runtime.h>
#include <cuda_fp16.h>
#include <math.h>
#include <cstdint>

#define NROWS 8192
#define DDIM  128
#define NTILE (NROWS / 128)               // 64 slabs of 128 rows
#define NTRI  (NTILE * (NTILE + 1) / 2)   // 2080 tiles

// dynamic smem layout for k_sim
#define SM_A    0                         // 128 rows x 256B f16 tile
#define SM_B    32768
#define SM_RED  65536
#define SM_REDC 66048
#define SM_TOT  66560

// ---------------- scratch (init-free or self-resetting) ---------------------
__device__ __half g_h[NROWS * DDIM];      // normalized * sqrt(log2e), f16
__device__ float  g_denom[NROWS];         // zeroed by k_normalize each run
__device__ float  g_M[2 * DDIM];          // class sums; reset by final finisher
__device__ int    g_ncnt[2];              // class counts; reset by final finisher
__device__ float  g_Lpart[NTILE][2];      // per-slab gated log sums
__device__ int    g_slabcnt[NTILE];       // reset by slab finisher
__device__ int    g_slabs;                // reset by final finisher
__device__ int    g_lblstride;

// ---------------- helpers ----------------------------------------------------
__device__ __forceinline__ uint32_t smem_u32(const void* p) {
    uint32_t a;
    asm("{ .reg .u64 t; cvta.to.shared.u64 t, %1; cvt.u32.u64 %0, t; }" : "=r"(a) : "l"(p));
    return a;
}
__device__ __forceinline__ float ex2f(float x) {
    float r;
    asm("ex2.approx.ftz.f32 %0, %1;" : "=f"(r) : "f"(x));
    return r;
}
__device__ __forceinline__ uint32_t h2exp2(uint32_t x) {   // ex2 on both halves
    uint32_t r;
    asm("ex2.approx.f16x2 %0, %1;" : "=r"(r) : "r"(x));
    return r;
}
__device__ __forceinline__ uint32_t h2add(uint32_t a, uint32_t b) {
    uint32_t r;
    asm("add.rn.f16x2 %0, %1, %2;" : "=r"(r) : "r"(a), "r"(b));
    return r;
}
__device__ __forceinline__ float2 h2tof2(uint32_t h) {
    __half2 v = *(__half2*)&h;
    return __half22float2(v);
}
__device__ __forceinline__ void ldsm_x4(uint32_t a, uint32_t& r0, uint32_t& r1,
                                        uint32_t& r2, uint32_t& r3) {
    asm volatile("ldmatrix.sync.aligned.m8n8.x4.shared.b16 {%0,%1,%2,%3}, [%4];"
                 : "=r"(r0), "=r"(r1), "=r"(r2), "=r"(r3) : "r"(a));
}
__device__ __forceinline__ void ldsm_x2t(uint32_t a, uint32_t& r0, uint32_t& r1) {
    asm volatile("ldmatrix.sync.aligned.m8n8.x2.trans.shared.b16 {%0,%1}, [%2];"
                 : "=r"(r0), "=r"(r1) : "r"(a));
}
__device__ __forceinline__ void mma16816h(uint32_t* c, uint32_t a0, uint32_t a1,
                                          uint32_t a2, uint32_t a3,
                                          uint32_t b0, uint32_t b1) {
    asm volatile(
        "mma.sync.aligned.m16n8k16.row.col.f16.f16.f16.f16 "
        "{%0,%1}, {%2,%3,%4,%5}, {%6,%7}, {%0,%1};"
        : "+r"(c[0]), "+r"(c[1])
        : "r"(a0), "r"(a1), "r"(a2), "r"(a3), "r"(b0), "r"(b1));
}
__device__ __forceinline__ int get_label(const int* l32, int i) { return l32[i * g_lblstride]; }

// ---------------- K1: normalize -> f16*sqrt(log2e) + class sums + resets ----
// 128 blocks x 256 threads; block b owns rows [64b, 64b+64).
__global__ void __launch_bounds__(256) k_normalize(const float* __restrict__ emb,
                                                   const int* __restrict__ l32) {
    const float SQRT_LOG2E = 1.2011224087864498f;
    int tid = threadIdx.x;
    int wid = tid >> 5, lane = tid & 31;
    int b = blockIdx.x;

    __shared__ int sdet;
    __shared__ float sM[2 * DDIM];
    __shared__ int   scnt[2];
    if (tid == 0) sdet = 0;
    sM[tid] = 0.0f;
    if (tid < 2) scnt[tid] = 0;
    __syncthreads();
    // labels are 0/1; int64 LE => odd int32 words are 0 (reads ints [1..511])
    if (l32[2 * tid + 1] != 0) atomicOr(&sdet, 1);
    __syncthreads();
    int stride = sdet ? 1 : 2;
    if (tid == 0 && b == 0) g_lblstride = stride;

    if (tid < 64) g_denom[b * 64 + tid] = 0.0f;

    #pragma unroll
    for (int it = 0; it < 8; it++) {
        int row = b * 64 + wid * 8 + it;
        float4 v = ((const float4*)(emb + (size_t)row * DDIM))[lane];
        float ss = v.x * v.x + v.y * v.y + v.z * v.z + v.w * v.w;
        #pragma unroll
        for (int o = 16; o; o >>= 1) ss += __shfl_xor_sync(0xffffffffu, ss, o);
        float r = rsqrtf(ss);
        int d = lane * 4;
        float e0 = v.x * r, e1 = v.y * r, e2 = v.z * r, e3 = v.w * r;
        float s = r * SQRT_LOG2E;
        __half2 h01 = __floats2half2_rn(v.x * s, v.y * s);
        __half2 h23 = __floats2half2_rn(v.z * s, v.w * s);
        *(__half2*)&g_h[(size_t)row * DDIM + d]     = h01;
        *(__half2*)&g_h[(size_t)row * DDIM + d + 2] = h23;
        int c = (l32[row * stride] == 0) ? 0 : 1;
        if (lane == 0) atomicAdd(&scnt[c], 1);
        float* sMc = &sM[c * DDIM + d];
        atomicAdd(&sMc[0], e0);
        atomicAdd(&sMc[1], e1);
        atomicAdd(&sMc[2], e2);
        atomicAdd(&sMc[3], e3);
    }
    __syncthreads();
    atomicAdd(&g_M[tid], sM[tid]);
    if (tid < 2) atomicAdd(&g_ncnt[tid], scnt[tid]);
}

// ---------------- K2: f16 HMMA sim tiles + distributed loss tails -----------
// CTA = 128x128 tile; 8 warps as 2(m) x 4(n); warp tile 64x32; f16 acc.
// acc already equals sim*log2e -> ex2.approx.f16x2 directly (no I2F/FMUL).
__global__ void __launch_bounds__(256, 2) k_sim(const int* __restrict__ l32,
                                                float* __restrict__ out) {
    int idx = blockIdx.x;
    int bj = (int)((sqrtf(8.0f * (float)idx + 1.0f) - 1.0f) * 0.5f);
    while ((bj + 1) * (bj + 2) / 2 <= idx) bj++;
    while (bj * (bj + 1) / 2 > idx) bj--;
    int bi = idx - bj * (bj + 1) / 2;

    extern __shared__ char smem[];
    uint32_t sb = smem_u32(smem);
    float* red  = (float*)(smem + SM_RED);
    float* redc = (float*)(smem + SM_REDC);

    int tid = threadIdx.x;
    int wid = tid >> 5, lane = tid & 31;
    int i0 = bi * 128, j0 = bj * 128;
    bool diag = (bi == bj);

    if (tid < 128) { red[tid] = 0.0f; redc[tid] = 0.0f; }

    // tile loads: row-major 256B rows; 16B chunk c of row r stored at c^(r&7)
    {
        int row = tid >> 1, half = tid & 1;
        const uint4* arow = (const uint4*)&g_h[(size_t)(i0 + row) * DDIM];
        const uint4* brow = (const uint4*)&g_h[(size_t)(j0 + row) * DDIM];
        #pragma unroll
        for (int c = 0; c < 8; c++) {
            int chunk = half * 8 + c;
            uint32_t off = row * 256 + ((chunk ^ (row & 7)) << 4);
            *(uint4*)(smem + SM_A + off) = arow[chunk];
            *(uint4*)(smem + SM_B + off) = brow[chunk];
        }
    }
    __syncthreads();

    int m_off = (wid >> 2) * 64;       // 0 or 64
    int n_off = (wid & 3) * 32;        // 0,32,64,96

    uint32_t acc[4][4][2];
    #pragma unroll
    for (int mt = 0; mt < 4; mt++)
        #pragma unroll
        for (int nt = 0; nt < 4; nt++) { acc[mt][nt][0] = 0u; acc[mt][nt][1] = 0u; }

    uint32_t rowA = (uint32_t)(m_off + (lane & 15));
    uint32_t rowB = (uint32_t)(n_off + (lane & 7));
    uint32_t swz  = (uint32_t)(lane & 7);

    #pragma unroll
    for (int kk = 0; kk < 8; kk++) {
        uint32_t a0[4], a1[4], a2[4], a3[4];
        #pragma unroll
        for (int mt = 0; mt < 4; mt++) {
            uint32_t chunk = (uint32_t)(kk * 2 + (lane >> 4));
            uint32_t addr = sb + SM_A + (rowA + mt * 16) * 256 + ((chunk ^ swz) << 4);
            ldsm_x4(addr, a0[mt], a1[mt], a2[mt], a3[mt]);
        }
        uint32_t b0[4], b1[4];
        #pragma unroll
        for (int nt = 0; nt < 4; nt++) {
            uint32_t chunk = (uint32_t)(kk * 2 + ((lane >> 3) & 1));
            uint32_t addr = sb + SM_B + (rowB + nt * 8) * 256 + ((chunk ^ swz) << 4);
            ldsm_x2t(addr, b0[nt], b1[nt]);
        }
        #pragma unroll
        for (int mt = 0; mt < 4; mt++)
            #pragma unroll
            for (int nt = 0; nt < 4; nt++)
                mma16816h(acc[mt][nt], a0[mt], a1[mt], a2[mt], a3[mt], b0[nt], b1[nt]);
    }

    int lrow = lane >> 2;
    int lcol = (lane & 3) * 2;

    if (!diag) {
        // ---- fast path: native f16 exp + half2 partial sums ----
        uint32_t colp[4];
        #pragma unroll
        for (int nt = 0; nt < 4; nt++) colp[nt] = 0u;

        #pragma unroll
        for (int mt = 0; mt < 4; mt++) {
            uint32_t rp0 = 0u, rp1 = 0u;
            #pragma unroll
            for (int nt = 0; nt < 4; nt++) {
                uint32_t e0 = h2exp2(acc[mt][nt][0]);    // row lrow,   cols lcol,lcol+1
                uint32_t e1 = h2exp2(acc[mt][nt][1]);    // row lrow+8
                rp0 = h2add(rp0, e0);
                rp1 = h2add(rp1, e1);
                colp[nt] = h2add(colp[nt], h2add(e0, e1));
            }
            float2 f0 = h2tof2(rp0);
            float2 f1 = h2tof2(rp1);
            float s0 = f0.x + f0.y;
            float s1 = f1.x + f1.y;
            s0 += __shfl_xor_sync(0xffffffffu, s0, 1);
            s0 += __shfl_xor_sync(0xffffffffu, s0, 2);
            s1 += __shfl_xor_sync(0xffffffffu, s1, 1);
            s1 += __shfl_xor_sync(0xffffffffu, s1, 2);
            if ((lane & 3) == 0) {
                atomicAdd(&red[m_off + mt * 16 + lrow], s0);
                atomicAdd(&red[m_off + mt * 16 + lrow + 8], s1);
            }
        }
        #pragma unroll
        for (int nt = 0; nt < 4; nt++) {
            float2 cf = h2tof2(colp[nt]);
            #pragma unroll
            for (int h = 0; h < 2; h++) {
                float c = h ? cf.y : cf.x;
                c += __shfl_xor_sync(0xffffffffu, c, 4);
                c += __shfl_xor_sync(0xffffffffu, c, 8);
                c += __shfl_xor_sync(0xffffffffu, c, 16);
                if (lane < 4)
                    atomicAdd(&redc[n_off + nt * 8 + (lane & 3) * 2 + h], c);
            }
        }
    } else {
        // ---- diag slow path (64/2080 tiles): fp32 with exact masking ----
        #pragma unroll
        for (int mt = 0; mt < 4; mt++) {
            int grow0 = i0 + m_off + mt * 16 + lrow;
            float s0 = 0.0f, s1 = 0.0f;
            #pragma unroll
            for (int nt = 0; nt < 4; nt++) {
                int gcol = j0 + n_off + nt * 8 + lcol;
                float2 f0 = h2tof2(acc[mt][nt][0]);
                float2 f1 = h2tof2(acc[mt][nt][1]);
                float e0 = ex2f(f0.x), e1 = ex2f(f0.y);
                float e2 = ex2f(f1.x), e3 = ex2f(f1.y);
                if (gcol     == grow0)     e0 = 0.0f;
                if (gcol + 1 == grow0)     e1 = 0.0f;
                if (gcol     == grow0 + 8) e2 = 0.0f;
                if (gcol + 1 == grow0 + 8) e3 = 0.0f;
                s0 += e0 + e1;
                s1 += e2 + e3;
            }
            s0 += __shfl_xor_sync(0xffffffffu, s0, 1);
            s0 += __shfl_xor_sync(0xffffffffu, s0, 2);
            s1 += __shfl_xor_sync(0xffffffffu, s1, 1);
            s1 += __shfl_xor_sync(0xffffffffu, s1, 2);
            if ((lane & 3) == 0) {
                atomicAdd(&red[m_off + mt * 16 + lrow], s0);
                atomicAdd(&red[m_off + mt * 16 + lrow + 8], s1);
            }
        }
    }

    __syncthreads();
    if (tid < 128) {
        atomicAdd(&g_denom[i0 + tid], red[tid]);
        if (!diag) atomicAdd(&g_denom[j0 + tid], redc[tid]);
    }
    __syncthreads();                    // denom atomics issued before ticket

    // ---- slab tickets: 64th contributor processes the slab's logs ----
    __shared__ int s_fini, s_finj, s_final;
    __shared__ float wred[8];
    if (tid == 0) {
        __threadfence();
        s_fini = (atomicAdd(&g_slabcnt[bi], 1) == 63) ? 1 : 0;
        s_finj = (!diag && atomicAdd(&g_slabcnt[bj], 1) == 63) ? 1 : 0;
    }
    __syncthreads();
    int nfin = s_fini + s_finj;
    if (nfin == 0) return;

    __threadfence();                    // acquire: slab contributions visible
    #pragma unroll
    for (int which = 0; which < 2; which++) {
        int doit = (which == 0) ? s_fini : s_finj;
        int s    = (which == 0) ? bi : bj;
        if (!doit) continue;
        float l0 = 0.0f, l1 = 0.0f;
        if (tid < 128) {
            int row = s * 128 + tid;
            float li = logf(g_denom[row]);
            if (get_label(l32, row) == 0) l0 = li; else l1 = li;
        }
        #pragma unroll
        for (int o = 16; o; o >>= 1) {
            l0 += __shfl_xor_sync(0xffffffffu, l0, o);
            l1 += __shfl_xor_sync(0xffffffffu, l1, o);
        }
        if (lane == 0 && wid < 4) { wred[wid] = l0; wred[wid + 4] = l1; }
        __syncthreads();
        if (tid == 0) {
            g_Lpart[s][0] = wred[0] + wred[1] + wred[2] + wred[3];
            g_Lpart[s][1] = wred[4] + wred[5] + wred[6] + wred[7];
            g_slabcnt[s] = 0;                      // self-reset for next replay
        }
        __syncthreads();
    }

    // ---- final ticket: assemble the loss ----
    if (tid == 0) {
        __threadfence();
        int old = atomicAdd(&g_slabs, nfin);
        s_final = (old + nfin == NTILE) ? 1 : 0;
        if (s_final) g_slabs = 0;                  // self-reset
    }
    __syncthreads();
    if (!s_final) return;
    __threadfence();

    __shared__ float sm0[8], sm1[8], sL0[8], sL1[8];
    float Md = g_M[tid];
    g_M[tid] = 0.0f;                               // self-reset
    float q0 = (tid < 128) ? Md * Md : 0.0f;
    float q1 = (tid < 128) ? 0.0f : Md * Md;
    #pragma unroll
    for (int o = 16; o; o >>= 1) {
        q0 += __shfl_xor_sync(0xffffffffu, q0, o);
        q1 += __shfl_xor_sync(0xffffffffu, q1, o);
    }
    if (lane == 0) { sm0[wid] = q0; sm1[wid] = q1; }
    float L0 = 0.0f, L1 = 0.0f;
    if (tid < NTILE) { L0 = g_Lpart[tid][0]; L1 = g_Lpart[tid][1]; }
    #pragma unroll
    for (int o = 16; o; o >>= 1) {
        L0 += __shfl_xor_sync(0xffffffffu, L0, o);
        L1 += __shfl_xor_sync(0xffffffffu, L1, o);
    }
    if (lane == 0) { sL0[wid] = L0; sL1[wid] = L1; }
    __syncthreads();
    if (tid == 0) {
        float M0 = 0.0f, M1 = 0.0f, TL0 = 0.0f, TL1 = 0.0f;
        #pragma unroll
        for (int w = 0; w < 8; w++) {
            M0 += sm0[w]; M1 += sm1[w];
            TL0 += sL0[w]; TL1 += sL1[w];
        }
        float n0 = (float)g_ncnt[0], n1 = (float)g_ncnt[1];
        g_ncnt[0] = 0; g_ncnt[1] = 0;              // self-reset
        float loss0 = -M0 + n0 + (n0 - 1.0f) * TL0;
        float loss1 = -M1 + n1 + (n1 - 1.0f) * TL1;
        out[0] = loss0 / n0 + loss1;
    }
}

// ---------------- launch -----------------------------------------------------
extern "C" void kernel_launch(void* const* d_in, const int* in_sizes, int n_in,
                              void* d_out, int out_size) {
    const float* emb = (const float*)d_in[0];
    const int*   l32 = (const int*)d_in[1];
    float*       out = (float*)d_out;

    cudaFuncSetAttribute(k_sim, cudaFuncAttributeMaxDynamicSharedMemorySize, SM_TOT);

    k_normalize<<<128, 256>>>(emb, l32);
    k_sim<<<NTRI, 256, SM_TOT>>>(l32, out);
}

// round 13
// speedup vs baseline: 1.1529x; 1.0472x over previous
#include <cuda_runtime.h>
#include <cuda_fp16.h>
#include <math.h>
#include <cstdint>

#define NROWS 8192
#define DDIM  128
#define NTILE (NROWS / 128)               // 64 slabs of 128 rows

// dynamic smem layout for k_sim
#define SM_A    0                         // 256 rows x 256B f16 = 65536
#define SM_B    65536                     // 128 rows x 256B f16 = 32768
#define SM_RED  98304                     // 256 f32 row sums
#define SM_REDC 99328                     // 128 f32 col sums
#define SM_TOT  99840

// ---------------- scratch (init-free or self-resetting) ---------------------
__device__ __half g_h[NROWS * DDIM];      // normalized * sqrt(log2e), f16
__device__ float  g_denom[NROWS];         // zeroed by k_normalize each run
__device__ float  g_M[2 * DDIM];          // class sums; reset by final finisher
__device__ int    g_ncnt[2];              // class counts; reset by final finisher
__device__ float  g_Lpart[NTILE][2];      // per-slab gated log sums
__device__ int    g_slabcnt[NTILE];       // reset by slab finisher
__device__ int    g_slabs;                // reset by final finisher
__device__ int    g_lblstride;

// ---------------- helpers ----------------------------------------------------
__device__ __forceinline__ uint32_t smem_u32(const void* p) {
    uint32_t a;
    asm("{ .reg .u64 t; cvta.to.shared.u64 t, %1; cvt.u32.u64 %0, t; }" : "=r"(a) : "l"(p));
    return a;
}
__device__ __forceinline__ float ex2f(float x) {
    float r;
    asm("ex2.approx.ftz.f32 %0, %1;" : "=f"(r) : "f"(x));
    return r;
}
__device__ __forceinline__ void ldsm_x4(uint32_t a, uint32_t& r0, uint32_t& r1,
                                        uint32_t& r2, uint32_t& r3) {
    asm volatile("ldmatrix.sync.aligned.m8n8.x4.shared.b16 {%0,%1,%2,%3}, [%4];"
                 : "=r"(r0), "=r"(r1), "=r"(r2), "=r"(r3) : "r"(a));
}
__device__ __forceinline__ void ldsm_x4t(uint32_t a, uint32_t& r0, uint32_t& r1,
                                         uint32_t& r2, uint32_t& r3) {
    asm volatile("ldmatrix.sync.aligned.m8n8.x4.trans.shared.b16 {%0,%1,%2,%3}, [%4];"
                 : "=r"(r0), "=r"(r1), "=r"(r2), "=r"(r3) : "r"(a));
}
__device__ __forceinline__ void mma16816h(uint32_t* c, uint32_t a0, uint32_t a1,
                                          uint32_t a2, uint32_t a3,
                                          uint32_t b0, uint32_t b1) {
    asm volatile(
        "mma.sync.aligned.m16n8k16.row.col.f16.f16.f16.f16 "
        "{%0,%1}, {%2,%3,%4,%5}, {%6,%7}, {%0,%1};"
        : "+r"(c[0]), "+r"(c[1])
        : "r"(a0), "r"(a1), "r"(a2), "r"(a3), "r"(b0), "r"(b1));
}
__device__ __forceinline__ int get_label(const int* l32, int i) { return l32[i * g_lblstride]; }

// ---------------- K1: normalize -> f16*sqrt(log2e) + class sums + resets ----
// 128 blocks x 256 threads; block b owns rows [64b, 64b+64).
__global__ void __launch_bounds__(256) k_normalize(const float* __restrict__ emb,
                                                   const int* __restrict__ l32) {
    const float SQRT_LOG2E = 1.2011224087864498f;
    int tid = threadIdx.x;
    int wid = tid >> 5, lane = tid & 31;
    int b = blockIdx.x;

    __shared__ int sdet;
    __shared__ float sM[2 * DDIM];
    __shared__ int   scnt[2];
    if (tid == 0) sdet = 0;
    sM[tid] = 0.0f;
    if (tid < 2) scnt[tid] = 0;
    __syncthreads();
    // labels are 0/1; int64 LE => odd int32 words are 0 (reads ints [1..511])
    if (l32[2 * tid + 1] != 0) atomicOr(&sdet, 1);
    __syncthreads();
    int stride = sdet ? 1 : 2;
    if (tid == 0 && b == 0) g_lblstride = stride;

    if (tid < 64) g_denom[b * 64 + tid] = 0.0f;

    #pragma unroll
    for (int it = 0; it < 8; it++) {
        int row = b * 64 + wid * 8 + it;
        float4 v = ((const float4*)(emb + (size_t)row * DDIM))[lane];
        float ss = v.x * v.x + v.y * v.y + v.z * v.z + v.w * v.w;
        #pragma unroll
        for (int o = 16; o; o >>= 1) ss += __shfl_xor_sync(0xffffffffu, ss, o);
        float r = rsqrtf(ss);
        int d = lane * 4;
        float e0 = v.x * r, e1 = v.y * r, e2 = v.z * r, e3 = v.w * r;
        float s = r * SQRT_LOG2E;
        __half2 h01 = __floats2half2_rn(v.x * s, v.y * s);
        __half2 h23 = __floats2half2_rn(v.z * s, v.w * s);
        *(__half2*)&g_h[(size_t)row * DDIM + d]     = h01;
        *(__half2*)&g_h[(size_t)row * DDIM + d + 2] = h23;
        int c = (l32[row * stride] == 0) ? 0 : 1;
        if (lane == 0) atomicAdd(&scnt[c], 1);
        float* sMc = &sM[c * DDIM + d];
        atomicAdd(&sMc[0], e0);
        atomicAdd(&sMc[1], e1);
        atomicAdd(&sMc[2], e2);
        atomicAdd(&sMc[3], e3);
    }
    __syncthreads();
    atomicAdd(&g_M[tid], sM[tid]);
    if (tid < 2) atomicAdd(&g_ncnt[tid], scnt[tid]);
}

// ---------------- K2: f16 HMMA, CTA 256(m)x128(n) + distributed loss tails ---
// grid (bj, bi2), valid when bj >= 2*bi2. Halves h=0,1 are i-tiles 2*bi2+h.
// Warp layout: 8 warps as 4(m) x 2(n), warp tile 64x64, f16 accumulators.
// Slab s completes after 64-(s>>1) contributions -> finisher computes logs.
__global__ void __launch_bounds__(256, 2) k_sim(const int* __restrict__ l32,
                                                float* __restrict__ out) {
    int bj = blockIdx.x, bi2 = blockIdx.y;
    if (bj < 2 * bi2) return;

    extern __shared__ char smem[];
    uint32_t sb = smem_u32(smem);
    float* red  = (float*)(smem + SM_RED);
    float* redc = (float*)(smem + SM_REDC);

    int tid = threadIdx.x;
    int wid = tid >> 5, lane = tid & 31;
    int i0 = bi2 * 256, j0 = bj * 128;

    red[tid] = 0.0f;
    if (tid < 128) redc[tid] = 0.0f;

    // ---- tile loads (16B chunk c of row r stored at chunk c^(r&7)) ----
    {
        const uint4* arow = (const uint4*)&g_h[(size_t)(i0 + tid) * DDIM];
        #pragma unroll
        for (int c = 0; c < 16; c++) {
            uint32_t off = tid * 256 + ((c ^ (tid & 7)) << 4);
            *(uint4*)(smem + SM_A + off) = arow[c];
        }
        int row = tid >> 1, half = tid & 1;
        const uint4* brow = (const uint4*)&g_h[(size_t)(j0 + row) * DDIM];
        #pragma unroll
        for (int c = 0; c < 8; c++) {
            int chunk = half * 8 + c;
            uint32_t off = row * 256 + ((chunk ^ (row & 7)) << 4);
            *(uint4*)(smem + SM_B + off) = brow[chunk];
        }
    }
    __syncthreads();

    int mg = wid >> 1, ng = wid & 1;
    int m_off = mg * 64, n_off = ng * 64;
    int h = mg >> 1;
    bool skip = (bj == 2 * bi2) && (h == 1);
    bool diag = (2 * bi2 + h == bj);

    if (!skip) {
        uint32_t acc[4][8][2];
        #pragma unroll
        for (int mt = 0; mt < 4; mt++)
            #pragma unroll
            for (int nt = 0; nt < 8; nt++) { acc[mt][nt][0] = 0u; acc[mt][nt][1] = 0u; }

        uint32_t rowA = (uint32_t)(m_off + (lane & 15));
        uint32_t rowBbase = (uint32_t)(n_off + ((lane >> 4) << 3) + (lane & 7));
        uint32_t chA_sel = (uint32_t)(lane >> 4);
        uint32_t chB_sel = (uint32_t)((lane >> 3) & 1);

        #pragma unroll
        for (int kk = 0; kk < 8; kk++) {
            uint32_t a[4][4];
            #pragma unroll
            for (int mt = 0; mt < 4; mt++) {
                uint32_t r = rowA + mt * 16;
                uint32_t chunk = (uint32_t)(kk * 2) + chA_sel;
                uint32_t addr = sb + SM_A + r * 256 + ((chunk ^ (r & 7)) << 4);
                ldsm_x4(addr, a[mt][0], a[mt][1], a[mt][2], a[mt][3]);
            }
            uint32_t b[8][2];
            #pragma unroll
            for (int p = 0; p < 4; p++) {
                uint32_t r = rowBbase + (uint32_t)(p * 16);
                uint32_t chunk = (uint32_t)(kk * 2) + chB_sel;
                uint32_t addr = sb + SM_B + r * 256 + ((chunk ^ (r & 7)) << 4);
                ldsm_x4t(addr, b[2 * p][0], b[2 * p][1], b[2 * p + 1][0], b[2 * p + 1][1]);
            }
            #pragma unroll
            for (int mt = 0; mt < 4; mt++)
                #pragma unroll
                for (int nt = 0; nt < 8; nt++)
                    mma16816h(acc[mt][nt], a[mt][0], a[mt][1], a[mt][2], a[mt][3],
                              b[nt][0], b[nt][1]);
        }

        // ---- epilogue: ex2, row sums, col sums (fp32, as measured in R6) ----
        int lrow = lane >> 2;
        int lcol = (lane & 3) * 2;
        float colacc[8][2];
        #pragma unroll
        for (int nt = 0; nt < 8; nt++) { colacc[nt][0] = 0.0f; colacc[nt][1] = 0.0f; }

        #pragma unroll
        for (int mt = 0; mt < 4; mt++) {
            float s0 = 0.0f, s1 = 0.0f;
            int grow0 = i0 + m_off + mt * 16 + lrow;
            #pragma unroll
            for (int nt = 0; nt < 8; nt++) {
                int gcol = j0 + n_off + nt * 8 + lcol;
                float2 f0 = __half22float2(*(__half2*)&acc[mt][nt][0]); // row grow0
                float2 f1 = __half22float2(*(__half2*)&acc[mt][nt][1]); // row grow0+8
                float e0 = ex2f(f0.x), e1 = ex2f(f0.y);
                float e2 = ex2f(f1.x), e3 = ex2f(f1.y);
                if (diag) {
                    if (gcol     == grow0)     e0 = 0.0f;
                    if (gcol + 1 == grow0)     e1 = 0.0f;
                    if (gcol     == grow0 + 8) e2 = 0.0f;
                    if (gcol + 1 == grow0 + 8) e3 = 0.0f;
                }
                s0 += e0 + e1;
                s1 += e2 + e3;
                colacc[nt][0] += e0 + e2;
                colacc[nt][1] += e1 + e3;
            }
            s0 += __shfl_xor_sync(0xffffffffu, s0, 1);
            s0 += __shfl_xor_sync(0xffffffffu, s0, 2);
            s1 += __shfl_xor_sync(0xffffffffu, s1, 1);
            s1 += __shfl_xor_sync(0xffffffffu, s1, 2);
            if ((lane & 3) == 0) {
                atomicAdd(&red[m_off + mt * 16 + lrow], s0);
                atomicAdd(&red[m_off + mt * 16 + lrow + 8], s1);
            }
        }

        if (!diag) {
            #pragma unroll
            for (int nt = 0; nt < 8; nt++) {
                #pragma unroll
                for (int hh = 0; hh < 2; hh++) {
                    float c = colacc[nt][hh];
                    c += __shfl_xor_sync(0xffffffffu, c, 4);
                    c += __shfl_xor_sync(0xffffffffu, c, 8);
                    c += __shfl_xor_sync(0xffffffffu, c, 16);
                    if (lane < 4)
                        atomicAdd(&redc[n_off + nt * 8 + (lane & 3) * 2 + hh], c);
                }
            }
        }
    }

    __syncthreads();
    atomicAdd(&g_denom[i0 + tid], red[tid]);
    bool has_j = (bj != 2 * bi2);
    if (tid < 128 && has_j)
        atomicAdd(&g_denom[j0 + tid], redc[tid]);
    __syncthreads();                    // denom atomics issued before tickets

    // ---- slab tickets: thr(s) = 64 - (s>>1) contributions ----
    __shared__ int sfin[3];
    __shared__ float wred[8];
    int slabs_of[3] = { 2 * bi2, 2 * bi2 + 1, bj };
    if (tid == 0) {
        __threadfence();
        sfin[0] = (atomicAdd(&g_slabcnt[2 * bi2], 1) == (64 - bi2) - 1) ? 1 : 0;
        sfin[1] = 0; sfin[2] = 0;
        if (has_j) {
            sfin[1] = (atomicAdd(&g_slabcnt[2 * bi2 + 1], 1) == (64 - bi2) - 1) ? 1 : 0;
            sfin[2] = (atomicAdd(&g_slabcnt[bj], 1) == (64 - (bj >> 1)) - 1) ? 1 : 0;
        }
    }
    __syncthreads();
    int nfin = sfin[0] + sfin[1] + sfin[2];
    if (nfin == 0) return;

    __threadfence();                    // acquire: slab contributions visible
    #pragma unroll
    for (int which = 0; which < 3; which++) {
        if (!sfin[which]) continue;
        int s = slabs_of[which];
        float l0 = 0.0f, l1 = 0.0f;
        if (tid < 128) {
            int row = s * 128 + tid;
            float li = logf(g_denom[row]);
            if (get_label(l32, row) == 0) l0 = li; else l1 = li;
        }
        #pragma unroll
        for (int o = 16; o; o >>= 1) {
            l0 += __shfl_xor_sync(0xffffffffu, l0, o);
            l1 += __shfl_xor_sync(0xffffffffu, l1, o);
        }
        if (lane == 0 && wid < 4) { wred[wid] = l0; wred[wid + 4] = l1; }
        __syncthreads();
        if (tid == 0) {
            g_Lpart[s][0] = wred[0] + wred[1] + wred[2] + wred[3];
            g_Lpart[s][1] = wred[4] + wred[5] + wred[6] + wred[7];
            g_slabcnt[s] = 0;                      // self-reset for next replay
        }
        __syncthreads();
    }

    // ---- final ticket: assemble loss ----
    __shared__ int s_final;
    if (tid == 0) {
        __threadfence();
        int old = atomicAdd(&g_slabs, nfin);
        s_final = (old + nfin == NTILE) ? 1 : 0;
        if (s_final) g_slabs = 0;                  // self-reset
    }
    __syncthreads();
    if (!s_final) return;
    __threadfence();

    __shared__ float sm0[8], sm1[8], sL0[8], sL1[8];
    float Md = g_M[tid];
    g_M[tid] = 0.0f;                               // self-reset
    float q0 = (tid < 128) ? Md * Md : 0.0f;
    float q1 = (tid < 128) ? 0.0f : Md * Md;
    #pragma unroll
    for (int o = 16; o; o >>= 1) {
        q0 += __shfl_xor_sync(0xffffffffu, q0, o);
        q1 += __shfl_xor_sync(0xffffffffu, q1, o);
    }
    if (lane == 0) { sm0[wid] = q0; sm1[wid] = q1; }
    float L0 = 0.0f, L1 = 0.0f;
    if (tid < NTILE) { L0 = g_Lpart[tid][0]; L1 = g_Lpart[tid][1]; }
    #pragma unroll
    for (int o = 16; o; o >>= 1) {
        L0 += __shfl_xor_sync(0xffffffffu, L0, o);
        L1 += __shfl_xor_sync(0xffffffffu, L1, o);
    }
    if (lane == 0) { sL0[wid] = L0; sL1[wid] = L1; }
    __syncthreads();
    if (tid == 0) {
        float M0 = 0.0f, M1 = 0.0f, TL0 = 0.0f, TL1 = 0.0f;
        #pragma unroll
        for (int w = 0; w < 8; w++) {
            M0 += sm0[w]; M1 += sm1[w];
            TL0 += sL0[w]; TL1 += sL1[w];
        }
        float n0 = (float)g_ncnt[0], n1 = (float)g_ncnt[1];
        g_ncnt[0] = 0; g_ncnt[1] = 0;              // self-reset
        float loss0 = -M0 + n0 + (n0 - 1.0f) * TL0;
        float loss1 = -M1 + n1 + (n1 - 1.0f) * TL1;
        out[0] = loss0 / n0 + loss1;
    }
}

// ---------------- launch -----------------------------------------------------
extern "C" void kernel_launch(void* const* d_in, const int* in_sizes, int n_in,
                              void* d_out, int out_size) {
    const float* emb = (const float*)d_in[0];
    const int*   l32 = (const int*)d_in[1];
    float*       out = (float*)d_out;

    cudaFuncSetAttribute(k_sim, cudaFuncAttributeMaxDynamicSharedMemorySize, SM_TOT);

    k_normalize<<<128, 256>>>(emb, l32);
    dim3 grid(64, 32);                 // bj, bi2; invalid CTAs exit immediately
    k_sim<<<grid, 256, SM_TOT>>>(l32, out);
}